// round 10
// baseline (speedup 1.0000x reference)
#include <cuda_runtime.h>
#include <cuda_fp16.h>
#include <mma.h>
#include <math.h>

using namespace nvcuda;

#define NN 20000
#define EE 80000
#define GG 1000
#define FTOT 16
#define CSD 5
#define FCIN 75

// ---------------- device scratch (allocation-free contract) ----------------
__device__ float g_hA[NN * 64];
__device__ float g_hB[NN * 64];
__device__ float g_hid[(size_t)EE * 128];
__device__ __half g_Ph[(size_t)NN * 128 * 64];   // packed: (n,k,o) -> n*COLS + (k>>1)*2*MO + 2*o + (k&1)
__device__ float g_R[NN * 64];
__device__ float g_agg[NN * 64];
__device__ float g_gsum[GG * FCIN];
__device__ float g_gcnt[GG];

__device__ __forceinline__ float* hbuf(int s) { return s ? g_hB : g_hA; }
__device__ __forceinline__ float elu_f(float x) { return x > 0.f ? x : (expf(x) - 1.f); }

// ---------------- kernels ----------------

__global__ void init_h0_kernel(const float* __restrict__ x) {
    int idx = blockIdx.x * blockDim.x + threadIdx.x;
    if (idx >= NN * CSD) return;
    int n = idx / CSD, i = idx % CSD;
    g_hA[n * CSD + i] = x[n * FTOT + i];
}

// hid[e,k] = relu(b1[k] + sum_a ea[e,a]*w1[a,k])
__global__ void hid_kernel(const float* __restrict__ ea,
                           const float* __restrict__ w1,
                           const float* __restrict__ b1) {
    int e = blockIdx.x;
    int k = threadIdx.x;
    __shared__ float a[5];
    if (k < 5) a[k] = ea[e * 5 + k];
    __syncthreads();
    float s = b1[k];
#pragma unroll
    for (int i = 0; i < 5; i++) s = fmaf(a[i], w1[i * 128 + k], s);
    g_hid[(size_t)e * 128 + k] = fmaxf(s, 0.f);
}

// P[n,(k,o)] = sum_i h[n,i]*w2[k,i,o]  -> fp16 packed, computed with tf32 wmma tensor cores.
// Block tile: 64 nodes x 128 packed cols, 256 threads (8 warps).
// Warp w: m-tile (w&3)*16, n-cols (w>>2)*64 .. +63  (4 x 16x16 wmma tiles, k-loop over MI_P/8).
template <int MI, int MO, int MI_P>
__global__ __launch_bounds__(256) void p3_kernel(const float* __restrict__ w2, int insel) {
    const int COLS = 128 * MO;
    __shared__ float As[64 * MI_P];    // [node][i], row-major, ldm = MI_P
    __shared__ float BC[128 * 128];    // B tile [MI_P][128] during k-loop; C staging [64][128] after
    const float* h = hbuf(insel);
    int nb = blockIdx.y * 64;
    int qb = blockIdx.x * 128;
    int t = threadIdx.x;

    // load A tile (zero-pad i >= MI and nodes >= NN)
    for (int idx = t; idx < 64 * MI_P; idx += 256) {
        int n = idx / MI_P, i = idx % MI_P;
        As[idx] = (i < MI && nb + n < NN) ? h[(nb + n) * MI + i] : 0.f;
    }
    // load B tile: Bs[i][ql] = w2[(k*MI + i)*MO + o] with packed col mapping, pad i >= MI
    for (int idx = t; idx < MI_P * 128; idx += 256) {
        int i = idx >> 7, ql = idx & 127;
        float v = 0.f;
        if (i < MI) {
            int q = qb + ql;
            int kk = q / (2 * MO);
            int rem = q % (2 * MO);
            int o = rem >> 1;
            int k = 2 * kk + (rem & 1);
            v = w2[(k * MI + i) * MO + o];
        }
        BC[idx] = v;
    }
    __syncthreads();

    int wid = t >> 5;
    int mt = wid & 3;          // m-tile 0..3
    int nh = wid >> 2;         // n-half 0..1
    const float* a_base = &As[mt * 16 * MI_P];

    wmma::fragment<wmma::accumulator, 16, 16, 8, float> c_frag[4];
#pragma unroll
    for (int j = 0; j < 4; j++) wmma::fill_fragment(c_frag[j], 0.f);

#pragma unroll
    for (int ks = 0; ks < MI_P / 8; ks++) {
        wmma::fragment<wmma::matrix_a, 16, 16, 8, wmma::precision::tf32, wmma::row_major> a_frag;
        wmma::load_matrix_sync(a_frag, a_base + ks * 8, MI_P);
#pragma unroll
        for (int i = 0; i < a_frag.num_elements; i++)
            a_frag.x[i] = wmma::__float_to_tf32(a_frag.x[i]);
#pragma unroll
        for (int j = 0; j < 4; j++) {
            wmma::fragment<wmma::matrix_b, 16, 16, 8, wmma::precision::tf32, wmma::row_major> b_frag;
            wmma::load_matrix_sync(b_frag, &BC[(ks * 8) * 128 + (nh * 64 + j * 16)], 128);
#pragma unroll
            for (int i = 0; i < b_frag.num_elements; i++)
                b_frag.x[i] = wmma::__float_to_tf32(b_frag.x[i]);
            wmma::mma_sync(c_frag[j], a_frag, b_frag, c_frag[j]);
        }
    }
    __syncthreads();  // done reading B; reuse BC as C staging [64][128] float

#pragma unroll
    for (int j = 0; j < 4; j++)
        wmma::store_matrix_sync(&BC[(mt * 16) * 128 + (nh * 64 + j * 16)], c_frag[j], 128,
                                wmma::mem_row_major);
    __syncthreads();

    // convert to fp16 and write coalesced: 64 rows x 128 cols -> 64 x 64 half2
    for (int idx = t; idx < 64 * 64; idx += 256) {
        int row = idx >> 6, cp = idx & 63;
        int node = nb + row;
        if (node < NN) {
            __half2 h2 = __floats2half2_rn(BC[row * 128 + 2 * cp], BC[row * 128 + 2 * cp + 1]);
            *(unsigned*)&g_Ph[(size_t)node * COLS + qb + 2 * cp] = *(unsigned*)&h2;
        }
    }
}

// R[n,o] = h[n]@b2[:,o] ; agg[n,o] = bias[o] + h[n]@root[:,o]   (agg pre-seeded with root term)
template <int MI, int MO>
__global__ void rb_kernel(const float* __restrict__ b2,
                          const float* __restrict__ root,
                          const float* __restrict__ bias, int insel) {
    int idx = blockIdx.x * blockDim.x + threadIdx.x;
    if (idx >= NN * MO) return;
    int n = idx / MO, o = idx % MO;
    const float* h = hbuf(insel);
    float sr = 0.f, sa = bias[o];
#pragma unroll
    for (int i = 0; i < MI; i++) {
        float hv = h[n * MI + i];
        sr = fmaf(hv, b2[i * MO + o], sr);
        sa = fmaf(hv, root[i * MO + o], sa);
    }
    g_R[n * MO + o] = sr;
    g_agg[n * MO + o] = sa;
}

// msg[e,o] = R[src,o] + sum_k hid[e,k]*P[src,k,o]; atomic scatter to agg[dst]
template <int MO>
__global__ __launch_bounds__(256) void edge2_kernel(const int* __restrict__ ei) {
    const int EPB = 256 / MO;
    const int COLS = 128 * MO;
    __shared__ float hs[EPB][128];
    __shared__ int ssrc[EPB], sdst[EPB];
    int t = threadIdx.x;
    int e0 = blockIdx.x * EPB;
    {
        const float4* hv = (const float4*)&g_hid[(size_t)e0 * 128];
        float4* hsv = (float4*)hs;
        for (int idx = t; idx < EPB * 32; idx += 256) hsv[idx] = hv[idx];
    }
    if (t < EPB) {
        ssrc[t] = ei[e0 + t];
        sdst[t] = ei[EE + e0 + t];
    }
    __syncthreads();
    int le = t / MO, o = t % MO;
    int src = ssrc[le], dst = sdst[le];
    const __half2* Pp = (const __half2*)&g_Ph[(size_t)src * COLS + 2 * o];
    const float2* hvv = (const float2*)hs[le];
    float acc = g_R[src * MO + o];
    float acc2 = 0.f;
#pragma unroll 16
    for (int kk = 0; kk < 64; kk++) {
        float2 p = __half22float2(Pp[(size_t)kk * MO]);
        float2 hh = hvv[kk];
        acc = fmaf(hh.x, p.x, acc);
        acc2 = fmaf(hh.y, p.y, acc2);
    }
    atomicAdd(&g_agg[dst * MO + o], acc + acc2);
}

// h_out = elu(agg)
template <int MO>
__global__ void elu_kernel(int outsel) {
    int idx = blockIdx.x * blockDim.x + threadIdx.x;
    if (idx >= NN * MO) return;
    hbuf(outsel)[idx] = elu_f(g_agg[idx]);
}

__global__ void zero_pool_kernel() {
    int idx = blockIdx.x * blockDim.x + threadIdx.x;
    if (idx < GG * FCIN) g_gsum[idx] = 0.f;
    if (idx < GG) g_gcnt[idx] = 0.f;
}

__global__ void pool_scatter_kernel(const float* __restrict__ x,
                                    const int* __restrict__ batch, int hsel) {
    int idx = blockIdx.x * blockDim.x + threadIdx.x;
    if (idx >= NN * FCIN) return;
    int n = idx / FCIN, d = idx % FCIN;
    const float* h = hbuf(hsel);
    float v = (d < 64) ? h[n * 64 + d] : x[n * FTOT + CSD + (d - 64)];
    int b = batch[n];
    atomicAdd(&g_gsum[b * FCIN + d], v);
    if (d == 0) atomicAdd(&g_gcnt[b], 1.f);
}

__global__ void mlp_kernel(const float* __restrict__ fc1w, const float* __restrict__ fc1b,
                           const float* __restrict__ fc2w, const float* __restrict__ fc2b,
                           const float* __restrict__ fc3w, const float* __restrict__ fc3b,
                           float* __restrict__ out) {
    int g = blockIdx.x;
    int t = threadIdx.x;  // 32
    __shared__ float gv[FCIN], a1[32], a2[16];
    float cnt = fmaxf(g_gcnt[g], 1.f);
    for (int i = t; i < FCIN; i += 32) gv[i] = g_gsum[g * FCIN + i] / cnt;
    __syncthreads();
    {
        float s = fc1b[t];
        for (int i = 0; i < FCIN; i++) s = fmaf(gv[i], fc1w[i * 32 + t], s);
        a1[t] = elu_f(s);
    }
    __syncthreads();
    if (t < 16) {
        float s = fc2b[t];
#pragma unroll
        for (int i = 0; i < 32; i++) s = fmaf(a1[i], fc2w[i * 16 + t], s);
        a2[t] = elu_f(s);
    }
    __syncthreads();
    if (t == 0) {
        float s = fc3b[0];
#pragma unroll
        for (int i = 0; i < 16; i++) s = fmaf(a2[i], fc3w[i], s);
        out[g] = s;
    }
}

// ---------------- host side ----------------

template <int MI, int MO, int MI_P>
static void run_layer(const float* ea, const int* ei,
                      const float* w1, const float* b1,
                      const float* w2, const float* b2,
                      const float* root, const float* bias,
                      int insel, int outsel) {
    hid_kernel<<<EE, 128>>>(ea, w1, b1);
    dim3 pg(MO, (NN + 63) / 64);
    p3_kernel<MI, MO, MI_P><<<pg, 256>>>(w2, insel);
    rb_kernel<MI, MO><<<(NN * MO + 255) / 256, 256>>>(b2, root, bias, insel);
    edge2_kernel<MO><<<EE / (256 / MO), 256>>>(ei);
    elu_kernel<MO><<<(NN * MO + 255) / 256, 256>>>(outsel);
}

extern "C" void kernel_launch(void* const* d_in, const int* in_sizes, int n_in,
                              void* d_out, int out_size) {
    const float* x  = (const float*)d_in[0];
    const int*   ei = (const int*)d_in[1];
    const float* ea = (const float*)d_in[2];
    const int*   batch = (const int*)d_in[3];

    const float* c1w1 = (const float*)d_in[4];
    const float* c1b1 = (const float*)d_in[5];
    const float* c1w2 = (const float*)d_in[6];
    const float* c1b2 = (const float*)d_in[7];
    const float* c1root = (const float*)d_in[8];
    const float* c1bias = (const float*)d_in[9];

    const float* c2w1 = (const float*)d_in[10];
    const float* c2b1 = (const float*)d_in[11];
    const float* c2w2 = (const float*)d_in[12];
    const float* c2b2 = (const float*)d_in[13];
    const float* c2root = (const float*)d_in[14];
    const float* c2bias = (const float*)d_in[15];

    const float* c3w1 = (const float*)d_in[16];
    const float* c3b1 = (const float*)d_in[17];
    const float* c3w2 = (const float*)d_in[18];
    const float* c3b2 = (const float*)d_in[19];
    const float* c3root = (const float*)d_in[20];
    const float* c3bias = (const float*)d_in[21];

    const float* fc1w = (const float*)d_in[22];
    const float* fc1b = (const float*)d_in[23];
    const float* fc2w = (const float*)d_in[24];
    const float* fc2b = (const float*)d_in[25];
    const float* fc3w = (const float*)d_in[26];
    const float* fc3b = (const float*)d_in[27];

    init_h0_kernel<<<(NN * CSD + 255) / 256, 256>>>(x);

    run_layer<5, 32, 8>(ea, ei, c1w1, c1b1, c1w2, c1b2, c1root, c1bias, 0, 1);
    run_layer<32, 64, 32>(ea, ei, c2w1, c2b1, c2w2, c2b2, c2root, c2bias, 1, 0);
    run_layer<64, 64, 64>(ea, ei, c3w1, c3b1, c3w2, c3b2, c3root, c3bias, 0, 1);

    zero_pool_kernel<<<(GG * FCIN + 255) / 256, 256>>>();
    pool_scatter_kernel<<<(NN * FCIN + 255) / 256, 256>>>(x, batch, 1);
    mlp_kernel<<<GG, 32>>>(fc1w, fc1b, fc2w, fc2b, fc3w, fc3b, (float*)d_out);
}

// round 11
// speedup vs baseline: 1.4664x; 1.4664x over previous
#include <cuda_runtime.h>
#include <cuda_fp16.h>
#include <mma.h>
#include <math.h>

using namespace nvcuda;

#define NN 20000
#define EE 80000
#define GG 1000
#define FTOT 16
#define CSD 5
#define FCIN 75

// ---------------- device scratch (allocation-free contract) ----------------
__device__ float g_hA[NN * 64];
__device__ float g_hB[NN * 64];
__device__ __half g_hH[NN * 64];                 // fp16 h, padded [n][MI_P]
__device__ __half g_w2h[64 * 128 * 64];          // fp16 w2 in packed-col layout [i][q], 1 MB max
__device__ float g_hid[(size_t)EE * 128];
__device__ __half g_Ph[(size_t)NN * 128 * 64];   // packed: (n,k,o) -> n*COLS + (k>>1)*2*MO + 2*o + (k&1)
__device__ float g_R[NN * 64];
__device__ float g_agg[NN * 64];
__device__ float g_gsum[GG * FCIN];
__device__ float g_gcnt[GG];

__device__ __forceinline__ float* hbuf(int s) { return s ? g_hB : g_hA; }
__device__ __forceinline__ float elu_f(float x) { return x > 0.f ? x : (expf(x) - 1.f); }

// ---------------- kernels ----------------

__global__ void init_h0_kernel(const float* __restrict__ x) {
    int idx = blockIdx.x * blockDim.x + threadIdx.x;
    if (idx >= NN * CSD) return;
    int n = idx / CSD, i = idx % CSD;
    g_hA[n * CSD + i] = x[n * FTOT + i];
}

// hid[e,k] = relu(b1[k] + sum_a ea[e,a]*w1[a,k])
__global__ void hid_kernel(const float* __restrict__ ea,
                           const float* __restrict__ w1,
                           const float* __restrict__ b1) {
    int e = blockIdx.x;
    int k = threadIdx.x;
    __shared__ float a[5];
    if (k < 5) a[k] = ea[e * 5 + k];
    __syncthreads();
    float s = b1[k];
#pragma unroll
    for (int i = 0; i < 5; i++) s = fmaf(a[i], w1[i * 128 + k], s);
    g_hid[(size_t)e * 128 + k] = fmaxf(s, 0.f);
}

// h (fp32, stride MI) -> g_hH (fp16, stride MI_P, zero-padded)
template <int MI, int MI_P>
__global__ void convh_kernel(int insel) {
    int idx = blockIdx.x * blockDim.x + threadIdx.x;
    if (idx >= NN * MI_P) return;
    int n = idx / MI_P, i = idx % MI_P;
    const float* h = hbuf(insel);
    g_hH[idx] = (i < MI) ? __float2half(h[n * MI + i]) : __half(0.f);
}

// w2 -> g_w2h[i*COLS + q] (fp16, packed-col layout, zero-padded i >= MI)
template <int MI, int MO, int MI_P>
__global__ void convw2_kernel(const float* __restrict__ w2) {
    const int COLS = 128 * MO;
    int idx = blockIdx.x * blockDim.x + threadIdx.x;
    if (idx >= MI_P * COLS) return;
    int i = idx / COLS, q = idx % COLS;
    float v = 0.f;
    if (i < MI) {
        int kk = q / (2 * MO);
        int rem = q % (2 * MO);
        int o = rem >> 1;
        int k = 2 * kk + (rem & 1);
        v = w2[(k * MI + i) * MO + o];
    }
    g_w2h[idx] = __float2half(v);
}

// P = h @ w2  (fp16 HMMA wmma m16n16k16, fp32 accum) -> fp16 packed g_Ph
// Block: 64 nodes x 128 packed cols, 8 warps; warp (mt, nh): m-tile mt*16, cols nh*64..+63.
template <int MI_P, int MO>
__global__ __launch_bounds__(256) void p4_kernel() {
    const int COLS = 128 * MO;
    __shared__ __half Ah[64 * MI_P];
    __shared__ float CsBs[64 * 128];         // first B tile (fp16), then C staging (fp32)
    __half* Bh = (__half*)CsBs;
    int nb = blockIdx.y * 64;
    int qb = blockIdx.x * 128;
    int t = threadIdx.x;

    // A tile: 64 rows x MI_P halves, contiguous per row (uint4 = 8 halves)
    {
        const int AV = 64 * MI_P / 8;
        uint4* Av = (uint4*)Ah;
        for (int idx = t; idx < AV; idx += 256) {
            int n = idx / (MI_P / 8);
            int node = nb + n;
            if (node < NN)
                Av[idx] = ((const uint4*)g_hH)[(size_t)node * (MI_P / 8) + (idx % (MI_P / 8))];
            else
                Av[idx] = make_uint4(0, 0, 0, 0);
        }
    }
    // B tile: MI_P rows x 128 halves from g_w2h[i*COLS + qb ...]
    {
        uint4* Bv = (uint4*)Bh;
        for (int idx = t; idx < MI_P * 16; idx += 256) {
            int i = idx / 16, v = idx % 16;
            Bv[idx] = ((const uint4*)(g_w2h + (size_t)i * COLS + qb))[v];
        }
    }
    __syncthreads();

    int wid = t >> 5;
    int mt = wid & 3;
    int nh = wid >> 2;

    wmma::fragment<wmma::accumulator, 16, 16, 16, float> c_frag[4];
#pragma unroll
    for (int j = 0; j < 4; j++) wmma::fill_fragment(c_frag[j], 0.f);

#pragma unroll
    for (int ks = 0; ks < MI_P / 16; ks++) {
        wmma::fragment<wmma::matrix_a, 16, 16, 16, __half, wmma::row_major> a_frag;
        wmma::load_matrix_sync(a_frag, &Ah[(mt * 16) * MI_P + ks * 16], MI_P);
#pragma unroll
        for (int j = 0; j < 4; j++) {
            wmma::fragment<wmma::matrix_b, 16, 16, 16, __half, wmma::row_major> b_frag;
            wmma::load_matrix_sync(b_frag, &Bh[(ks * 16) * 128 + (nh * 64 + j * 16)], 128);
            wmma::mma_sync(c_frag[j], a_frag, b_frag, c_frag[j]);
        }
    }
    __syncthreads();  // B tile no longer needed

#pragma unroll
    for (int j = 0; j < 4; j++)
        wmma::store_matrix_sync(&CsBs[(mt * 16) * 128 + (nh * 64 + j * 16)], c_frag[j], 128,
                                wmma::mem_row_major);
    __syncthreads();

    for (int idx = t; idx < 64 * 64; idx += 256) {
        int row = idx >> 6, cp = idx & 63;
        int node = nb + row;
        if (node < NN) {
            __half2 h2 = __floats2half2_rn(CsBs[row * 128 + 2 * cp], CsBs[row * 128 + 2 * cp + 1]);
            *(unsigned*)&g_Ph[(size_t)node * COLS + qb + 2 * cp] = *(unsigned*)&h2;
        }
    }
}

// R[n,o] = h[n]@b2[:,o] ; agg[n,o] = bias[o] + h[n]@root[:,o]
template <int MI, int MO>
__global__ void rb_kernel(const float* __restrict__ b2,
                          const float* __restrict__ root,
                          const float* __restrict__ bias, int insel) {
    int idx = blockIdx.x * blockDim.x + threadIdx.x;
    if (idx >= NN * MO) return;
    int n = idx / MO, o = idx % MO;
    const float* h = hbuf(insel);
    float sr = 0.f, sa = bias[o];
#pragma unroll
    for (int i = 0; i < MI; i++) {
        float hv = h[n * MI + i];
        sr = fmaf(hv, b2[i * MO + o], sr);
        sa = fmaf(hv, root[i * MO + o], sa);
    }
    g_R[n * MO + o] = sr;
    g_agg[n * MO + o] = sa;
}

// msg[e,o] = R[src,o] + sum_k hid[e,k]*P[src,k,o]; atomic scatter to agg[dst]
template <int MO>
__global__ __launch_bounds__(256) void edge2_kernel(const int* __restrict__ ei) {
    const int EPB = 256 / MO;
    const int COLS = 128 * MO;
    __shared__ float hs[EPB][128];
    __shared__ int ssrc[EPB], sdst[EPB];
    int t = threadIdx.x;
    int e0 = blockIdx.x * EPB;
    {
        const float4* hv = (const float4*)&g_hid[(size_t)e0 * 128];
        float4* hsv = (float4*)hs;
        for (int idx = t; idx < EPB * 32; idx += 256) hsv[idx] = hv[idx];
    }
    if (t < EPB) {
        ssrc[t] = ei[e0 + t];
        sdst[t] = ei[EE + e0 + t];
    }
    __syncthreads();
    int le = t / MO, o = t % MO;
    int src = ssrc[le], dst = sdst[le];
    const __half2* Pp = (const __half2*)&g_Ph[(size_t)src * COLS + 2 * o];
    const float2* hvv = (const float2*)hs[le];
    float acc = g_R[src * MO + o];
    float acc2 = 0.f;
#pragma unroll 16
    for (int kk = 0; kk < 64; kk++) {
        float2 p = __half22float2(Pp[(size_t)kk * MO]);
        float2 hh = hvv[kk];
        acc = fmaf(hh.x, p.x, acc);
        acc2 = fmaf(hh.y, p.y, acc2);
    }
    atomicAdd(&g_agg[dst * MO + o], acc + acc2);
}

// h_out = elu(agg)
template <int MO>
__global__ void elu_kernel(int outsel) {
    int idx = blockIdx.x * blockDim.x + threadIdx.x;
    if (idx >= NN * MO) return;
    hbuf(outsel)[idx] = elu_f(g_agg[idx]);
}

__global__ void zero_pool_kernel() {
    int idx = blockIdx.x * blockDim.x + threadIdx.x;
    if (idx < GG * FCIN) g_gsum[idx] = 0.f;
    if (idx < GG) g_gcnt[idx] = 0.f;
}

__global__ void pool_scatter_kernel(const float* __restrict__ x,
                                    const int* __restrict__ batch, int hsel) {
    int idx = blockIdx.x * blockDim.x + threadIdx.x;
    if (idx >= NN * FCIN) return;
    int n = idx / FCIN, d = idx % FCIN;
    const float* h = hbuf(hsel);
    float v = (d < 64) ? h[n * 64 + d] : x[n * FTOT + CSD + (d - 64)];
    int b = batch[n];
    atomicAdd(&g_gsum[b * FCIN + d], v);
    if (d == 0) atomicAdd(&g_gcnt[b], 1.f);
}

__global__ void mlp_kernel(const float* __restrict__ fc1w, const float* __restrict__ fc1b,
                           const float* __restrict__ fc2w, const float* __restrict__ fc2b,
                           const float* __restrict__ fc3w, const float* __restrict__ fc3b,
                           float* __restrict__ out) {
    int g = blockIdx.x;
    int t = threadIdx.x;  // 32
    __shared__ float gv[FCIN], a1[32], a2[16];
    float cnt = fmaxf(g_gcnt[g], 1.f);
    for (int i = t; i < FCIN; i += 32) gv[i] = g_gsum[g * FCIN + i] / cnt;
    __syncthreads();
    {
        float s = fc1b[t];
        for (int i = 0; i < FCIN; i++) s = fmaf(gv[i], fc1w[i * 32 + t], s);
        a1[t] = elu_f(s);
    }
    __syncthreads();
    if (t < 16) {
        float s = fc2b[t];
#pragma unroll
        for (int i = 0; i < 32; i++) s = fmaf(a1[i], fc2w[i * 16 + t], s);
        a2[t] = elu_f(s);
    }
    __syncthreads();
    if (t == 0) {
        float s = fc3b[0];
#pragma unroll
        for (int i = 0; i < 16; i++) s = fmaf(a2[i], fc3w[i], s);
        out[g] = s;
    }
}

// ---------------- host side ----------------

template <int MI, int MO, int MI_P>
static void run_layer(const float* ea, const int* ei,
                      const float* w1, const float* b1,
                      const float* w2, const float* b2,
                      const float* root, const float* bias,
                      int insel, int outsel) {
    hid_kernel<<<EE, 128>>>(ea, w1, b1);
    convh_kernel<MI, MI_P><<<(NN * MI_P + 255) / 256, 256>>>(insel);
    convw2_kernel<MI, MO, MI_P><<<(MI_P * 128 * MO + 255) / 256, 256>>>(w2);
    dim3 pg(MO, (NN + 63) / 64);
    p4_kernel<MI_P, MO><<<pg, 256>>>();
    rb_kernel<MI, MO><<<(NN * MO + 255) / 256, 256>>>(b2, root, bias, insel);
    edge2_kernel<MO><<<EE / (256 / MO), 256>>>(ei);
    elu_kernel<MO><<<(NN * MO + 255) / 256, 256>>>(outsel);
}

extern "C" void kernel_launch(void* const* d_in, const int* in_sizes, int n_in,
                              void* d_out, int out_size) {
    const float* x  = (const float*)d_in[0];
    const int*   ei = (const int*)d_in[1];
    const float* ea = (const float*)d_in[2];
    const int*   batch = (const int*)d_in[3];

    const float* c1w1 = (const float*)d_in[4];
    const float* c1b1 = (const float*)d_in[5];
    const float* c1w2 = (const float*)d_in[6];
    const float* c1b2 = (const float*)d_in[7];
    const float* c1root = (const float*)d_in[8];
    const float* c1bias = (const float*)d_in[9];

    const float* c2w1 = (const float*)d_in[10];
    const float* c2b1 = (const float*)d_in[11];
    const float* c2w2 = (const float*)d_in[12];
    const float* c2b2 = (const float*)d_in[13];
    const float* c2root = (const float*)d_in[14];
    const float* c2bias = (const float*)d_in[15];

    const float* c3w1 = (const float*)d_in[16];
    const float* c3b1 = (const float*)d_in[17];
    const float* c3w2 = (const float*)d_in[18];
    const float* c3b2 = (const float*)d_in[19];
    const float* c3root = (const float*)d_in[20];
    const float* c3bias = (const float*)d_in[21];

    const float* fc1w = (const float*)d_in[22];
    const float* fc1b = (const float*)d_in[23];
    const float* fc2w = (const float*)d_in[24];
    const float* fc2b = (const float*)d_in[25];
    const float* fc3w = (const float*)d_in[26];
    const float* fc3b = (const float*)d_in[27];

    init_h0_kernel<<<(NN * CSD + 255) / 256, 256>>>(x);

    run_layer<5, 32, 16>(ea, ei, c1w1, c1b1, c1w2, c1b2, c1root, c1bias, 0, 1);
    run_layer<32, 64, 32>(ea, ei, c2w1, c2b1, c2w2, c2b2, c2root, c2bias, 1, 0);
    run_layer<64, 64, 64>(ea, ei, c3w1, c3b1, c3w2, c3b2, c3root, c3bias, 0, 1);

    zero_pool_kernel<<<(GG * FCIN + 255) / 256, 256>>>();
    pool_scatter_kernel<<<(NN * FCIN + 255) / 256, 256>>>(x, batch, 1);
    mlp_kernel<<<GG, 32>>>(fc1w, fc1b, fc2w, fc2b, fc3w, fc3b, (float*)d_out);
}